// round 11
// baseline (speedup 1.0000x reference)
#include <cuda_runtime.h>
#include <cuda_bf16.h>

#define NLVL   4
#define BATCH  4
#define NBOX   128
#define MAXBS  64
#define CROP   14
#define CCH    256
#define NSLOTS (NLVL * BATCH * MAXBS)          // 1024
#define PTS    (CROP * CROP)                   // 196
#define C4     (CCH / 4)                       // 64 float4 per point
#define NT     (PTS / 4)                       // 49 tiles of 4 points per slot
#define GT     7                               // tiles per block
#define NGRP   (NT / GT)                       // 7 groups per slot
#define GPTS   (GT * 4)                        // 28 points per block

// ---------------------------------------------------------------------------
// Single fused kernel: one block per (slot, tile-group of 7).
// Block->slot mapping is permuted so consecutive blocks cycle through
// (lvl, b) fastest and rank slowest: every 16 consecutive blocks mix all
// levels/batches, blending read-heavy (lvl0), L2-hot (lvl3) and store-only
// (empty rank) work within each scheduling wave.
// ---------------------------------------------------------------------------
__global__ void __launch_bounds__(256)
roi_kernel(const float* __restrict__ f0, const float* __restrict__ f1,
           const float* __restrict__ f2, const float* __restrict__ f3,
           const float* __restrict__ db, float* __restrict__ out) {
    __shared__ int    s_map[MAXBS];  // rank -> box index
    __shared__ int    s_filled;
    __shared__ int4   s_off[GPTS];   // o00,o01,o10,o11 (float4 units)
    __shared__ float2 s_w[GPTS];     // wx, wy
    __shared__ int    s_vld[GPTS];

    // permuted decode: lvl,b fastest; rank slowest
    int x    = blockIdx.x;                    // 0..1023
    int lvl  = x & 3;
    int b    = (x >> 2) & 3;
    int rank = x >> 4;                        // 0..63
    int slotIdx = (lvl << 8) | (b << 6) | rank;   // output slot index

    int grp  = blockIdx.y;                    // 0..6
    int pin  = threadIdx.x >> 6;              // point within tile (0..3)
    int c4   = threadIdx.x & 63;
    int lane = threadIdx.x & 31;

    // ---- warp 0: ballot prefix scan over this (b,lvl)'s 128 boxes ----
    if (threadIdx.x < 32) {
        float flvl = (float)lvl;
        int rank_base = 0;
        #pragma unroll
        for (int k = 0; k < 4; ++k) {
            int n = k * 32 + lane;
            float id = __ldg(db + (b * NBOX + n) * 7 + 0);
            bool m = (id == flvl);
            unsigned mask = __ballot_sync(0xffffffffu, m);
            int r = rank_base + __popc(mask & ((1u << lane) - 1u));
            if (m && r < MAXBS) s_map[r] = n;
            rank_base += __popc(mask);
        }
        if (lane == 0) s_filled = rank_base < MAXBS ? rank_base : MAXBS;
    }
    __syncthreads();

    int filled = s_filled;
    int n = (rank < filled) ? s_map[rank] : -1;

    // ---- boxes output: 16 designated blocks write their (b,lvl) stripe ----
    if (grp == 0 && rank == 0) {
        float* ob_base = out + (size_t)NSLOTS * PTS * CCH
                       + ((size_t)(b * NLVL + lvl) * MAXBS) * 6;
        for (int i = threadIdx.x; i < MAXBS * 6; i += 256) {
            int r = i / 6;
            int q = i - r * 6;
            float v = 0.0f;
            if (r < filled) v = __ldg(db + (b * NBOX + s_map[r]) * 7 + 1 + q);
            ob_base[i] = v;
        }
    }

    float4* base = reinterpret_cast<float4*>(out)
                 + (size_t)slotIdx * (PTS * C4) + (grp * GT * 4 + pin) * C4 + c4;
    const int TS = 4 * C4;                    // tile stride in float4

    if (n < 0) {                              // empty slot: streaming zeros
        float4 z = make_float4(0.f, 0.f, 0.f, 0.f);
        #pragma unroll
        for (int t = 0; t < GT; ++t) __stcs(base + t * TS, z);
        return;
    }

    int H = 256 >> lvl;

    if (threadIdx.x < GPTS) {
        const float* bx = db + (b * NBOX + n) * 7;
        float cx = bx[1], cy = bx[2], w = bx[3], h = bx[4];

        float y1n = (cy - h * 0.5f) / 1023.0f;
        float y2n = (cy + h * 0.5f) / 1023.0f;
        float x1n = (cx - w * 0.5f) / 1023.0f;
        float x2n = (cx + w * 0.5f) / 1023.0f;

        float S = (float)(H - 1);
        int pt  = grp * GPTS + threadIdx.x;   // global point index
        int py  = pt / CROP;
        int px  = pt - py * CROP;
        float ty = (float)py * (1.0f / 13.0f);
        float tx = (float)px * (1.0f / 13.0f);

        float ys = y1n * S + ty * ((y2n - y1n) * S);
        float xs = x1n * S + tx * ((x2n - x1n) * S);

        s_vld[threadIdx.x] = (ys >= 0.0f && ys <= S && xs >= 0.0f && xs <= S);

        float y0f = floorf(ys), x0f = floorf(xs);
        s_w[threadIdx.x] = make_float2(xs - x0f, ys - y0f);

        int y0 = (int)y0f; y0 = y0 < 0 ? 0 : (y0 > H - 1 ? H - 1 : y0);
        int yb = y0 + 1;   yb = yb > H - 1 ? H - 1 : yb;
        int x0 = (int)x0f; x0 = x0 < 0 ? 0 : (x0 > H - 1 ? H - 1 : x0);
        int xb = x0 + 1;   xb = xb > H - 1 ? H - 1 : xb;

        int rowT = (b * H + y0) * H;
        int rowB = (b * H + yb) * H;
        s_off[threadIdx.x] = make_int4((rowT + x0) * C4, (rowT + xb) * C4,
                                       (rowB + x0) * C4, (rowB + xb) * C4);
    }
    __syncthreads();

    const float* fm = (lvl == 0) ? f0 : (lvl == 1) ? f1 : (lvl == 2) ? f2 : f3;
    const float4* fv = reinterpret_cast<const float4*>(fm);

    // ---- pipeline prologue: fetch local tile 0 ----
    float4 a00, a01, a10, a11;
    float2 wcur;
    int    vcur;
    {
        int4 o = s_off[pin];
        wcur = s_w[pin];
        vcur = s_vld[pin];
        a00 = __ldg(fv + o.x + c4);
        a01 = __ldg(fv + o.y + c4);
        a10 = __ldg(fv + o.z + c4);
        a11 = __ldg(fv + o.w + c4);
    }

    #pragma unroll
    for (int t = 0; t < GT - 1; ++t) {
        // ---- prefetch local tile t+1 ----
        int np = (t + 1) * 4 + pin;
        int4 o = s_off[np];
        float2 wnxt = s_w[np];
        int    vnxt = s_vld[np];
        float4 b00 = __ldg(fv + o.x + c4);
        float4 b01 = __ldg(fv + o.y + c4);
        float4 b10 = __ldg(fv + o.z + c4);
        float4 b11 = __ldg(fv + o.w + c4);

        // ---- compute + store local tile t ----
        float wx = wcur.x, wy = wcur.y;
        float ax = 1.0f - wx;
        float ay = 1.0f - wy;

        float4 r;
        r.x = (a00.x * ax + a01.x * wx) * ay + (a10.x * ax + a11.x * wx) * wy;
        r.y = (a00.y * ax + a01.y * wx) * ay + (a10.y * ax + a11.y * wx) * wy;
        r.z = (a00.z * ax + a01.z * wx) * ay + (a10.z * ax + a11.z * wx) * wy;
        r.w = (a00.w * ax + a01.w * wx) * ay + (a10.w * ax + a11.w * wx) * wy;
        if (!vcur) r = make_float4(0.f, 0.f, 0.f, 0.f);
        __stcs(base + t * TS, r);

        // ---- shift ----
        a00 = b00; a01 = b01; a10 = b10; a11 = b11;
        wcur = wnxt; vcur = vnxt;
    }

    // ---- epilogue: local tile GT-1 ----
    {
        float wx = wcur.x, wy = wcur.y;
        float ax = 1.0f - wx;
        float ay = 1.0f - wy;

        float4 r;
        r.x = (a00.x * ax + a01.x * wx) * ay + (a10.x * ax + a11.x * wx) * wy;
        r.y = (a00.y * ax + a01.y * wx) * ay + (a10.y * ax + a11.y * wx) * wy;
        r.z = (a00.z * ax + a01.z * wx) * ay + (a10.z * ax + a11.z * wx) * wy;
        r.w = (a00.w * ax + a01.w * wx) * ay + (a10.w * ax + a11.w * wx) * wy;
        if (!vcur) r = make_float4(0.f, 0.f, 0.f, 0.f);
        __stcs(base + (GT - 1) * TS, r);
    }
}

extern "C" void kernel_launch(void* const* d_in, const int* in_sizes, int n_in,
                              void* d_out, int out_size) {
    const float* f0 = (const float*)d_in[0];
    const float* f1 = (const float*)d_in[1];
    const float* f2 = (const float*)d_in[2];
    const float* f3 = (const float*)d_in[3];
    const float* db = (const float*)d_in[4];

    float* out = (float*)d_out;

    dim3 grid(NSLOTS, NGRP);
    roi_kernel<<<grid, 256>>>(f0, f1, f2, f3, db, out);
}